// round 4
// baseline (speedup 1.0000x reference)
#include <cuda_runtime.h>

#define HH 8
#define BB 2
#define LL 256
#define DD 512
#define DK 64
#define BH (BB*HH)

// Scratch (allocation-free rule: __device__ globals)
__device__ float g_q[BH*LL*DK];
__device__ float g_k[BH*LL*DK];
__device__ float g_v[BH*LL*DK];
__device__ float g_ctx[BH*LL*DK];

#define BM 64
#define BN 64
#define BK 16

// ---------------------------------------------------------------------------
// Fused Q/K/V projection: Y = X @ W^T + b, scattered into [B*H, L, dk] layout.
// gridDim.z selects which of q/k/v.
// ---------------------------------------------------------------------------
__global__ void proj_kernel(const float* __restrict__ q_in, const float* __restrict__ k_in,
                            const float* __restrict__ v_in,
                            const float* __restrict__ Wq, const float* __restrict__ bq,
                            const float* __restrict__ Wk, const float* __restrict__ bk,
                            const float* __restrict__ Wv, const float* __restrict__ bv)
{
    const int which = blockIdx.z;
    const float* X    = which == 0 ? q_in : (which == 1 ? k_in : v_in);
    const float* W    = which == 0 ? Wq   : (which == 1 ? Wk   : Wv);
    const float* bias = which == 0 ? bq   : (which == 1 ? bk   : bv);
    float*       Y    = which == 0 ? g_q  : (which == 1 ? g_k  : g_v);

    __shared__ float Xs[BK][BM + 1];
    __shared__ float Ws[BK][BN + 1];

    const int tx = threadIdx.x, ty = threadIdx.y;
    const int tid = ty * 16 + tx;
    const int m0 = blockIdx.y * BM;
    const int n0 = blockIdx.x * BN;

    float acc[4][4] = {};

    for (int k0 = 0; k0 < DD; k0 += BK) {
        #pragma unroll
        for (int r = 0; r < 4; r++) {
            int idx = tid + 256 * r;
            int kk = idx & 15;
            int row = idx >> 4;
            Xs[kk][row] = X[(m0 + row) * DD + k0 + kk];
            Ws[kk][row] = W[(n0 + row) * DD + k0 + kk];
        }
        __syncthreads();
        #pragma unroll
        for (int kk = 0; kk < BK; kk++) {
            float a[4], bv2[4];
            #pragma unroll
            for (int i = 0; i < 4; i++) a[i] = Xs[kk][ty + 16 * i];
            #pragma unroll
            for (int j = 0; j < 4; j++) bv2[j] = Ws[kk][tx + 16 * j];
            #pragma unroll
            for (int i = 0; i < 4; i++)
                #pragma unroll
                for (int j = 0; j < 4; j++)
                    acc[i][j] += a[i] * bv2[j];
        }
        __syncthreads();
    }

    #pragma unroll
    for (int i = 0; i < 4; i++) {
        int m = m0 + ty + 16 * i;     // m = b*L + l
        int b = m / LL, l = m % LL;
        #pragma unroll
        for (int j = 0; j < 4; j++) {
            int e = n0 + tx + 16 * j;
            int h = e / DK, d = e % DK;
            Y[((size_t)(b * HH + h) * LL + l) * DK + d] = acc[i][j] + bias[e];
        }
    }
}

// ---------------------------------------------------------------------------
// Fused attention core: one CTA per (bh, i).
//   scores_j = scale*(q_i . k_j) + q_i . rel_q[bh,i,j,:]  (mask applied)
//   p = softmax(scores);  ctx = sum_j p_j * (v_j + rel_v[bh,i,j,:])
// HBM-bound on rel_q/rel_v (512 MB); streamed via __ldcs (evict-first) so
// the L2-resident k/v tiles (reused 256x) aren't thrashed.
// ---------------------------------------------------------------------------
__global__ void attn_kernel(const int* __restrict__ mask,
                            const float* __restrict__ rq,
                            const float* __restrict__ rv)
{
    const int i  = blockIdx.x;
    const int bh = blockIdx.y;
    const int b  = bh / HH;
    const int tid  = threadIdx.x;
    const int warp = tid >> 5;
    const int lane = tid & 31;

    __shared__ float qs[DK];
    __shared__ float sc[LL];
    __shared__ float redm[8];
    __shared__ float reds[8];
    __shared__ float cpart[8][DK];

    if (tid < DK) qs[tid] = g_q[((size_t)bh * LL + i) * DK + tid];
    __syncthreads();

    const float2 q2 = *(const float2*)&qs[2 * lane];
    const float scale = 0.125f;   // 1/sqrt(64)
    const size_t rbase = ((size_t)bh * LL + i) * (size_t)LL * DK;

    // ---- scores: warp per j, 5-step shfl reduce ----
    #pragma unroll 4
    for (int j = warp; j < LL; j += 8) {
        const float2 k2 = *(const float2*)&g_k[((size_t)bh * LL + j) * DK + 2 * lane];
        const float2 r2 = __ldcs((const float2*)&rq[rbase + (size_t)j * DK + 2 * lane]);
        float p = q2.x * (scale * k2.x + r2.x) + q2.y * (scale * k2.y + r2.y);
        #pragma unroll
        for (int off = 16; off > 0; off >>= 1)
            p += __shfl_down_sync(0xffffffffu, p, off);
        if (lane == 0) {
            sc[j] = (__ldcs(&mask[(b * LL + i) * LL + j]) == 0) ? -1e9f : p;
        }
    }
    __syncthreads();

    // ---- softmax over 256 (one score per thread) ----
    const float sv = sc[tid];
    float m = sv;
    #pragma unroll
    for (int off = 16; off > 0; off >>= 1)
        m = fmaxf(m, __shfl_xor_sync(0xffffffffu, m, off));
    if (lane == 0) redm[warp] = m;
    __syncthreads();
    float bm = redm[0];
    #pragma unroll
    for (int w = 1; w < 8; w++) bm = fmaxf(bm, redm[w]);

    const float e = __expf(sv - bm);
    float s = e;
    #pragma unroll
    for (int off = 16; off > 0; off >>= 1)
        s += __shfl_xor_sync(0xffffffffu, s, off);
    if (lane == 0) reds[warp] = s;
    __syncthreads();
    float tot = 0.f;
    #pragma unroll
    for (int w = 0; w < 8; w++) tot += reds[w];
    sc[tid] = e / tot;        // each thread rewrites only its own slot
    __syncthreads();

    // ---- context: warp per j, accumulate p_j * (v_j + rel_v) ----
    float2 acc = make_float2(0.f, 0.f);
    #pragma unroll 4
    for (int j = warp; j < LL; j += 8) {
        const float pj = sc[j];
        const float2 v2 = *(const float2*)&g_v[((size_t)bh * LL + j) * DK + 2 * lane];
        const float2 r2 = __ldcs((const float2*)&rv[rbase + (size_t)j * DK + 2 * lane]);
        acc.x += pj * (v2.x + r2.x);
        acc.y += pj * (v2.y + r2.y);
    }
    cpart[warp][2 * lane]     = acc.x;
    cpart[warp][2 * lane + 1] = acc.y;
    __syncthreads();

    if (tid < DK) {
        float ssum = 0.f;
        #pragma unroll
        for (int w = 0; w < 8; w++) ssum += cpart[w][tid];
        g_ctx[((size_t)bh * LL + i) * DK + tid] = ssum;
    }
}

// ---------------------------------------------------------------------------
// Output projection: gather ctx [B*H, L, dk] -> [B*L, D], out = X @ Wo^T + bo
// ---------------------------------------------------------------------------
__global__ void out_kernel(const float* __restrict__ Wo, const float* __restrict__ bo,
                           float* __restrict__ out)
{
    __shared__ float Xs[BK][BM + 1];
    __shared__ float Ws[BK][BN + 1];

    const int tx = threadIdx.x, ty = threadIdx.y;
    const int tid = ty * 16 + tx;
    const int m0 = blockIdx.y * BM;
    const int n0 = blockIdx.x * BN;

    float acc[4][4] = {};

    for (int k0 = 0; k0 < DD; k0 += BK) {
        #pragma unroll
        for (int r = 0; r < 4; r++) {
            int idx = tid + 256 * r;
            int kk = idx & 15;
            int row = idx >> 4;
            int m = m0 + row;
            int b = m / LL, l = m % LL;
            int kg = k0 + kk;
            int h = kg / DK, d = kg & (DK - 1);
            Xs[kk][row] = g_ctx[((size_t)(b * HH + h) * LL + l) * DK + d];
            Ws[kk][row] = Wo[(n0 + row) * DD + kg];
        }
        __syncthreads();
        #pragma unroll
        for (int kk = 0; kk < BK; kk++) {
            float a[4], bv2[4];
            #pragma unroll
            for (int i = 0; i < 4; i++) a[i] = Xs[kk][ty + 16 * i];
            #pragma unroll
            for (int j = 0; j < 4; j++) bv2[j] = Ws[kk][tx + 16 * j];
            #pragma unroll
            for (int i = 0; i < 4; i++)
                #pragma unroll
                for (int j = 0; j < 4; j++)
                    acc[i][j] += a[i] * bv2[j];
        }
        __syncthreads();
    }

    #pragma unroll
    for (int i = 0; i < 4; i++) {
        int m = m0 + ty + 16 * i;
        #pragma unroll
        for (int j = 0; j < 4; j++) {
            int e = n0 + tx + 16 * j;
            out[(size_t)m * DD + e] = acc[i][j] + bo[e];
        }
    }
}

extern "C" void kernel_launch(void* const* d_in, const int* in_sizes, int n_in,
                              void* d_out, int out_size)
{
    const float* query = (const float*)d_in[0];
    const float* key   = (const float*)d_in[1];
    const float* value = (const float*)d_in[2];
    const int*   mask  = (const int*)d_in[3];
    const float* rq    = (const float*)d_in[4];
    const float* rv    = (const float*)d_in[5];
    const float* Wq    = (const float*)d_in[6];
    const float* bq    = (const float*)d_in[7];
    const float* Wk    = (const float*)d_in[8];
    const float* bk    = (const float*)d_in[9];
    const float* Wv    = (const float*)d_in[10];
    const float* bv    = (const float*)d_in[11];
    const float* Wo    = (const float*)d_in[12];
    const float* bo    = (const float*)d_in[13];
    float* out = (float*)d_out;

    proj_kernel<<<dim3(DD / BN, (BB * LL) / BM, 3), dim3(16, 16)>>>(
        query, key, value, Wq, bq, Wk, bk, Wv, bv);
    attn_kernel<<<dim3(LL, BH), 256>>>(mask, rq, rv);
    out_kernel<<<dim3(DD / BN, (BB * LL) / BM), dim3(16, 16)>>>(Wo, bo, out);
}

// round 5
// speedup vs baseline: 1.3582x; 1.3582x over previous
#include <cuda_runtime.h>

#define HH 8
#define BB 2
#define LL 256
#define DD 512
#define DK 64
#define BH (BB*HH)

// Scratch (allocation-free rule: __device__ globals)
__device__ float g_q[BH*LL*DK];
__device__ float g_k[BH*LL*DK];
__device__ float g_v[BH*LL*DK];
__device__ float g_ctx[BH*LL*DK];

// ---------------------------------------------------------------------------
// GEMM tiles: 32(M) x 64(N), 128 threads, 4x4 per thread, BK=16.
// Inner loop: 2x LDS.128 per 16 FMA. Grid: proj (8,16,3)=384, out (8,16)=128.
// ---------------------------------------------------------------------------
#define PBK 16

// Fused Q/K/V projection: Y = X @ W^T + b, scattered into [B*H, L, dk].
__global__ void __launch_bounds__(128) proj_kernel(
    const float* __restrict__ q_in, const float* __restrict__ k_in,
    const float* __restrict__ v_in,
    const float* __restrict__ Wq, const float* __restrict__ bq,
    const float* __restrict__ Wk, const float* __restrict__ bk,
    const float* __restrict__ Wv, const float* __restrict__ bv)
{
    const int which = blockIdx.z;
    const float* X    = which == 0 ? q_in : (which == 1 ? k_in : v_in);
    const float* W    = which == 0 ? Wq   : (which == 1 ? Wk   : Wv);
    const float* bias = which == 0 ? bq   : (which == 1 ? bk   : bv);
    float*       Y    = which == 0 ? g_q  : (which == 1 ? g_k  : g_v);

    __shared__ float Xs[PBK][32 + 4];
    __shared__ float Ws[PBK][64 + 4];

    const int tid = threadIdx.x;
    const int tx = tid & 15;      // N quad
    const int ty = tid >> 4;      // M quad (0..7)
    const int m0 = blockIdx.y * 32;
    const int n0 = blockIdx.x * 64;

    float4 acc0 = {0,0,0,0}, acc1 = {0,0,0,0}, acc2 = {0,0,0,0}, acc3 = {0,0,0,0};

    for (int k0 = 0; k0 < DD; k0 += PBK) {
        // X tile: 32 rows x 16 -> 128 float4, 1 per thread
        {
            int r = tid >> 2, c4 = tid & 3;
            float4 x = *(const float4*)&X[(size_t)(m0 + r) * DD + k0 + c4 * 4];
            Xs[c4*4+0][r] = x.x; Xs[c4*4+1][r] = x.y;
            Xs[c4*4+2][r] = x.z; Xs[c4*4+3][r] = x.w;
        }
        // W tile: 64 rows x 16 -> 256 float4, 2 per thread
        #pragma unroll
        for (int t = 0; t < 2; t++) {
            int idx = tid + 128 * t;
            int r = idx >> 2, c4 = idx & 3;
            float4 w = *(const float4*)&W[(size_t)(n0 + r) * DD + k0 + c4 * 4];
            Ws[c4*4+0][r] = w.x; Ws[c4*4+1][r] = w.y;
            Ws[c4*4+2][r] = w.z; Ws[c4*4+3][r] = w.w;
        }
        __syncthreads();
        #pragma unroll
        for (int kk = 0; kk < PBK; kk++) {
            float4 a = *(const float4*)&Xs[kk][ty * 4];
            float4 b = *(const float4*)&Ws[kk][tx * 4];
            acc0.x += a.x*b.x; acc0.y += a.x*b.y; acc0.z += a.x*b.z; acc0.w += a.x*b.w;
            acc1.x += a.y*b.x; acc1.y += a.y*b.y; acc1.z += a.y*b.z; acc1.w += a.y*b.w;
            acc2.x += a.z*b.x; acc2.y += a.z*b.y; acc2.z += a.z*b.z; acc2.w += a.z*b.w;
            acc3.x += a.w*b.x; acc3.y += a.w*b.y; acc3.z += a.w*b.z; acc3.w += a.w*b.w;
        }
        __syncthreads();
    }

    const int e0 = n0 + tx * 4;            // col quad, within one head
    const int h = e0 >> 6, d = e0 & 63;
    float4 b4 = *(const float4*)&bias[e0];
    float4 accs[4] = {acc0, acc1, acc2, acc3};
    #pragma unroll
    for (int i = 0; i < 4; i++) {
        int m = m0 + ty * 4 + i;
        int b = m >> 8, l = m & 255;
        float4 o;
        o.x = accs[i].x + b4.x; o.y = accs[i].y + b4.y;
        o.z = accs[i].z + b4.z; o.w = accs[i].w + b4.w;
        *(float4*)&Y[((size_t)(b * HH + h) * LL + l) * DK + d] = o;
    }
}

// ---------------------------------------------------------------------------
// Fused attention core: one CTA per (bh, i). float4 everywhere; each warp
// processes 2 j-rows per iteration (half-warp per j). rel tensors streamed
// with __ldcs. 16 iters/warp, unroll 8 -> deep MLP to cover DRAM latency.
// ---------------------------------------------------------------------------
__global__ void __launch_bounds__(256) attn_kernel(
    const int* __restrict__ mask,
    const float* __restrict__ rq,
    const float* __restrict__ rv)
{
    const int i  = blockIdx.x;
    const int bh = blockIdx.y;
    const int b  = bh >> 3;
    const int tid  = threadIdx.x;
    const int warp = tid >> 5;
    const int lane = tid & 31;
    const int half = lane >> 4;
    const int lq   = lane & 15;

    __shared__ float qs[DK];
    __shared__ float sc[LL];
    __shared__ float redm[8];
    __shared__ float reds[8];
    __shared__ float cpart[16][DK + 4];

    if (tid < DK) qs[tid] = g_q[((size_t)bh * LL + i) * DK + tid];
    __syncthreads();

    const float4 q4 = *(const float4*)&qs[lq * 4];
    const float scale = 0.125f;   // 1/sqrt(64)
    const size_t rbase = ((size_t)bh * LL + i) * (size_t)(LL * DK);
    const size_t kvbase = (size_t)bh * LL * DK;
    const int mrow = (b * LL + i) * LL;

    // ---- scores: each warp does 2 j per iter, width-16 shfl reduce ----
    #pragma unroll 8
    for (int it = 0; it < 16; it++) {
        const int j = it * 16 + warp * 2 + half;
        const float4 k4 = *(const float4*)&g_k[kvbase + (size_t)j * DK + lq * 4];
        const float4 r4 = __ldcs((const float4*)&rq[rbase + (size_t)j * DK + lq * 4]);
        float p = q4.x * (scale * k4.x + r4.x)
                + q4.y * (scale * k4.y + r4.y)
                + q4.z * (scale * k4.z + r4.z)
                + q4.w * (scale * k4.w + r4.w);
        p += __shfl_down_sync(0xffffffffu, p, 8, 16);
        p += __shfl_down_sync(0xffffffffu, p, 4, 16);
        p += __shfl_down_sync(0xffffffffu, p, 2, 16);
        p += __shfl_down_sync(0xffffffffu, p, 1, 16);
        if (lq == 0) {
            sc[j] = (__ldcs(&mask[mrow + j]) == 0) ? -1e9f : p;
        }
    }
    __syncthreads();

    // ---- softmax over 256 (one score per thread) ----
    const float sv = sc[tid];
    float m = sv;
    #pragma unroll
    for (int off = 16; off > 0; off >>= 1)
        m = fmaxf(m, __shfl_xor_sync(0xffffffffu, m, off));
    if (lane == 0) redm[warp] = m;
    __syncthreads();
    float bm = redm[0];
    #pragma unroll
    for (int w = 1; w < 8; w++) bm = fmaxf(bm, redm[w]);

    const float e = __expf(sv - bm);
    float s = e;
    #pragma unroll
    for (int off = 16; off > 0; off >>= 1)
        s += __shfl_xor_sync(0xffffffffu, s, off);
    if (lane == 0) reds[warp] = s;
    __syncthreads();
    float tot = 0.f;
    #pragma unroll
    for (int w = 0; w < 8; w++) tot += reds[w];
    sc[tid] = e / tot;
    __syncthreads();

    // ---- context: accumulate p_j * (v_j + rel_v), float4 per lane ----
    float4 acc = {0.f, 0.f, 0.f, 0.f};
    #pragma unroll 8
    for (int it = 0; it < 16; it++) {
        const int j = it * 16 + warp * 2 + half;
        const float pj = sc[j];
        const float4 v4 = *(const float4*)&g_v[kvbase + (size_t)j * DK + lq * 4];
        const float4 r4 = __ldcs((const float4*)&rv[rbase + (size_t)j * DK + lq * 4]);
        acc.x += pj * (v4.x + r4.x);
        acc.y += pj * (v4.y + r4.y);
        acc.z += pj * (v4.z + r4.z);
        acc.w += pj * (v4.w + r4.w);
    }
    *(float4*)&cpart[warp * 2 + half][lq * 4] = acc;
    __syncthreads();

    if (tid < DK) {
        float ssum = 0.f;
        #pragma unroll
        for (int p = 0; p < 16; p++) ssum += cpart[p][tid];
        g_ctx[((size_t)bh * LL + i) * DK + tid] = ssum;
    }
}

// ---------------------------------------------------------------------------
// Output projection: gather ctx [B*H, L, dk] -> out = ctx @ Wo^T + bo
// Same 32x64 / 128-thread / float4 microkernel as proj.
// ---------------------------------------------------------------------------
__global__ void __launch_bounds__(128) out_kernel(
    const float* __restrict__ Wo, const float* __restrict__ bo,
    float* __restrict__ out)
{
    __shared__ float Xs[PBK][32 + 4];
    __shared__ float Ws[PBK][64 + 4];

    const int tid = threadIdx.x;
    const int tx = tid & 15;
    const int ty = tid >> 4;
    const int m0 = blockIdx.y * 32;
    const int n0 = blockIdx.x * 64;

    float4 acc0 = {0,0,0,0}, acc1 = {0,0,0,0}, acc2 = {0,0,0,0}, acc3 = {0,0,0,0};

    for (int k0 = 0; k0 < DD; k0 += PBK) {
        // gather ctx tile: 32 rows x 16 cols
        {
            int r = tid >> 2, c4 = tid & 3;
            int mm = m0 + r;
            int bb = mm >> 8, l = mm & 255;
            int c = k0 + c4 * 4;             // col quad, one head
            int h = c >> 6, d = c & 63;
            float4 x = *(const float4*)&g_ctx[((size_t)(bb * HH + h) * LL + l) * DK + d];
            Xs[c4*4+0][r] = x.x; Xs[c4*4+1][r] = x.y;
            Xs[c4*4+2][r] = x.z; Xs[c4*4+3][r] = x.w;
        }
        #pragma unroll
        for (int t = 0; t < 2; t++) {
            int idx = tid + 128 * t;
            int r = idx >> 2, c4 = idx & 3;
            float4 w = *(const float4*)&Wo[(size_t)(n0 + r) * DD + k0 + c4 * 4];
            Ws[c4*4+0][r] = w.x; Ws[c4*4+1][r] = w.y;
            Ws[c4*4+2][r] = w.z; Ws[c4*4+3][r] = w.w;
        }
        __syncthreads();
        #pragma unroll
        for (int kk = 0; kk < PBK; kk++) {
            float4 a = *(const float4*)&Xs[kk][ty * 4];
            float4 b = *(const float4*)&Ws[kk][tx * 4];
            acc0.x += a.x*b.x; acc0.y += a.x*b.y; acc0.z += a.x*b.z; acc0.w += a.x*b.w;
            acc1.x += a.y*b.x; acc1.y += a.y*b.y; acc1.z += a.y*b.z; acc1.w += a.y*b.w;
            acc2.x += a.z*b.x; acc2.y += a.z*b.y; acc2.z += a.z*b.z; acc2.w += a.z*b.w;
            acc3.x += a.w*b.x; acc3.y += a.w*b.y; acc3.z += a.w*b.z; acc3.w += a.w*b.w;
        }
        __syncthreads();
    }

    const int e0 = n0 + tx * 4;
    float4 b4 = *(const float4*)&bo[e0];
    float4 accs[4] = {acc0, acc1, acc2, acc3};
    #pragma unroll
    for (int i = 0; i < 4; i++) {
        int m = m0 + ty * 4 + i;
        float4 o;
        o.x = accs[i].x + b4.x; o.y = accs[i].y + b4.y;
        o.z = accs[i].z + b4.z; o.w = accs[i].w + b4.w;
        *(float4*)&out[(size_t)m * DD + e0] = o;
    }
}

extern "C" void kernel_launch(void* const* d_in, const int* in_sizes, int n_in,
                              void* d_out, int out_size)
{
    const float* query = (const float*)d_in[0];
    const float* key   = (const float*)d_in[1];
    const float* value = (const float*)d_in[2];
    const int*   mask  = (const int*)d_in[3];
    const float* rq    = (const float*)d_in[4];
    const float* rv    = (const float*)d_in[5];
    const float* Wq    = (const float*)d_in[6];
    const float* bq    = (const float*)d_in[7];
    const float* Wk    = (const float*)d_in[8];
    const float* bk    = (const float*)d_in[9];
    const float* Wv    = (const float*)d_in[10];
    const float* bv    = (const float*)d_in[11];
    const float* Wo    = (const float*)d_in[12];
    const float* bo    = (const float*)d_in[13];
    float* out = (float*)d_out;

    proj_kernel<<<dim3(DD / 64, (BB * LL) / 32, 3), 128>>>(
        query, key, value, Wq, bq, Wk, bk, Wv, bv);
    attn_kernel<<<dim3(LL, BH), 256>>>(mask, rq, rv);
    out_kernel<<<dim3(DD / 64, (BB * LL) / 32), 128>>>(Wo, bo, out);
}